// round 4
// baseline (speedup 1.0000x reference)
#include <cuda_runtime.h>
#include <cuda_bf16.h>

#define N_T   21
#define SEQ   1024
#define DIMC  3072
#define NH    24
#define HDIM  128
#define ENCC  768
#define NAK   32
#define NTOK  (N_T * SEQ)          /* 21504 */
#define ENCR  (N_T * NAK)          /* 672 */

// ---------------- scratch (device globals: allocation-free) ----------------
__device__ float g_Q [(size_t)NTOK * DIMC];
__device__ float g_O [(size_t)NTOK * DIMC];
__device__ float g_KV[(size_t)ENCR * 2 * DIMC];
__device__ float g_minmax[4];

// ---------------- min/max of the two x_ref_attn_map rows -------------------
__global__ void minmax_kernel(const float* __restrict__ xmap) {
    int row = blockIdx.x;
    const float* p = xmap + row * NTOK;
    float mn = 3.4e38f, mx = -3.4e38f;
    for (int i = threadIdx.x; i < NTOK; i += blockDim.x) {
        float v = p[i];
        mn = fminf(mn, v); mx = fmaxf(mx, v);
    }
    __shared__ float smn[32], smx[32];
    int lane = threadIdx.x & 31, w = threadIdx.x >> 5;
    #pragma unroll
    for (int o = 16; o; o >>= 1) {
        mn = fminf(mn, __shfl_xor_sync(0xffffffffu, mn, o));
        mx = fmaxf(mx, __shfl_xor_sync(0xffffffffu, mx, o));
    }
    if (lane == 0) { smn[w] = mn; smx[w] = mx; }
    __syncthreads();
    if (w == 0) {
        int nw = blockDim.x >> 5;
        mn = (lane < nw) ? smn[lane] :  3.4e38f;
        mx = (lane < nw) ? smx[lane] : -3.4e38f;
        #pragma unroll
        for (int o = 16; o; o >>= 1) {
            mn = fminf(mn, __shfl_xor_sync(0xffffffffu, mn, o));
            mx = fmaxf(mx, __shfl_xor_sync(0xffffffffu, mx, o));
        }
        if (lane == 0) { g_minmax[row * 2] = mn; g_minmax[row * 2 + 1] = mx; }
    }
}

// ------------- 3xBF16-split GEMM:  C[M,N] = A[M,K] @ B[N,K]^T + bias -------
#define BM 128
#define BN 128
#define BKK 32
#define KS 20   /* smem row stride in bf16x2 words: 16 used + 4 pad */

__device__ __forceinline__ unsigned pack_bf2(float x, float y) {
    __nv_bfloat162 t = __floats2bfloat162_rn(x, y);
    return *reinterpret_cast<unsigned*>(&t);
}

__device__ __forceinline__ void mma_bf16(float* c, const unsigned* a, unsigned b0, unsigned b1) {
    asm volatile(
        "mma.sync.aligned.m16n8k16.row.col.f32.bf16.bf16.f32 "
        "{%0,%1,%2,%3}, {%4,%5,%6,%7}, {%8,%9}, {%0,%1,%2,%3};\n"
        : "+f"(c[0]), "+f"(c[1]), "+f"(c[2]), "+f"(c[3])
        : "r"(a[0]), "r"(a[1]), "r"(a[2]), "r"(a[3]), "r"(b0), "r"(b1));
}

__global__ __launch_bounds__(256) void gemm_split_bf16(
    const float* __restrict__ A, const float* __restrict__ B,
    const float* __restrict__ bias, float* __restrict__ C,
    int M, int N, int K)
{
    __shared__ unsigned Ah[BM][KS], Al[BM][KS], Bh[BN][KS], Bl[BN][KS];

    int tid  = threadIdx.x;
    int warp = tid >> 5, lane = tid & 31;
    int wm = warp >> 1, wn = warp & 1;           // 4x2 warps; warp tile 32x64
    int quad = lane >> 2, t4 = lane & 3;
    int m0 = blockIdx.y * BM, n0 = blockIdx.x * BN;

    float acc[2][8][4];
    #pragma unroll
    for (int i = 0; i < 2; i++)
        #pragma unroll
        for (int j = 0; j < 8; j++)
            #pragma unroll
            for (int c = 0; c < 4; c++) acc[i][j][c] = 0.f;

    float4 pa[4], pb[4];

    auto loadAB = [&](int kk) {
        #pragma unroll
        for (int i = 0; i < 4; i++) {
            int idx = tid + i * 256;
            int r = idx >> 3, c4 = (idx & 7) * 4;
            int gm = m0 + r;
            if (gm < M) pa[i] = *(const float4*)(A + (size_t)gm * K + kk + c4);
            else        pa[i] = make_float4(0.f, 0.f, 0.f, 0.f);
            pb[i] = *(const float4*)(B + (size_t)(n0 + r) * K + kk + c4);
        }
    };
    auto storeAB = [&]() {
        #pragma unroll
        for (int i = 0; i < 4; i++) {
            int idx = tid + i * 256;
            int r = idx >> 3, c4 = (idx & 7) * 4;
            int k2 = c4 >> 1;
            float4 v = pa[i];
            float hx = __bfloat162float(__float2bfloat16(v.x));
            float hy = __bfloat162float(__float2bfloat16(v.y));
            float hz = __bfloat162float(__float2bfloat16(v.z));
            float hw = __bfloat162float(__float2bfloat16(v.w));
            Ah[r][k2]     = pack_bf2(v.x, v.y);
            Ah[r][k2 + 1] = pack_bf2(v.z, v.w);
            Al[r][k2]     = pack_bf2(v.x - hx, v.y - hy);
            Al[r][k2 + 1] = pack_bf2(v.z - hz, v.w - hw);
            v = pb[i];
            hx = __bfloat162float(__float2bfloat16(v.x));
            hy = __bfloat162float(__float2bfloat16(v.y));
            hz = __bfloat162float(__float2bfloat16(v.z));
            hw = __bfloat162float(__float2bfloat16(v.w));
            Bh[r][k2]     = pack_bf2(v.x, v.y);
            Bh[r][k2 + 1] = pack_bf2(v.z, v.w);
            Bl[r][k2]     = pack_bf2(v.x - hx, v.y - hy);
            Bl[r][k2 + 1] = pack_bf2(v.z - hz, v.w - hw);
        }
    };

    int nk = K / BKK;
    loadAB(0);
    storeAB();
    __syncthreads();

    for (int t = 0; t < nk; t++) {
        if (t + 1 < nk) loadAB((t + 1) * BKK);

        #pragma unroll
        for (int ks = 0; ks < 2; ks++) {
            int kb = ks * 8;
            unsigned ah[2][4], al[2][4];
            #pragma unroll
            for (int mi = 0; mi < 2; mi++) {
                int r = wm * 32 + mi * 16;
                ah[mi][0] = Ah[r + quad    ][kb + t4];
                ah[mi][1] = Ah[r + quad + 8][kb + t4];
                ah[mi][2] = Ah[r + quad    ][kb + t4 + 4];
                ah[mi][3] = Ah[r + quad + 8][kb + t4 + 4];
                al[mi][0] = Al[r + quad    ][kb + t4];
                al[mi][1] = Al[r + quad + 8][kb + t4];
                al[mi][2] = Al[r + quad    ][kb + t4 + 4];
                al[mi][3] = Al[r + quad + 8][kb + t4 + 4];
            }
            #pragma unroll
            for (int ni = 0; ni < 8; ni++) {
                int cb = wn * 64 + ni * 8;
                unsigned bh0 = Bh[cb + quad][kb + t4], bh1 = Bh[cb + quad][kb + t4 + 4];
                unsigned bl0 = Bl[cb + quad][kb + t4], bl1 = Bl[cb + quad][kb + t4 + 4];
                #pragma unroll
                for (int mi = 0; mi < 2; mi++) {
                    mma_bf16(acc[mi][ni], ah[mi], bh0, bh1);
                    mma_bf16(acc[mi][ni], al[mi], bh0, bh1);
                    mma_bf16(acc[mi][ni], ah[mi], bl0, bl1);
                }
            }
        }

        if (t + 1 < nk) {
            __syncthreads();
            storeAB();
            __syncthreads();
        }
    }

    #pragma unroll
    for (int mi = 0; mi < 2; mi++) {
        int gm = m0 + wm * 32 + mi * 16 + quad;
        #pragma unroll
        for (int ni = 0; ni < 8; ni++) {
            int gn = n0 + wn * 64 + ni * 8 + t4 * 2;
            float b0v = bias[gn], b1v = bias[gn + 1];
            if (gm < M)
                *(float2*)(C + (size_t)gm * N + gn) =
                    make_float2(acc[mi][ni][0] + b0v, acc[mi][ni][1] + b1v);
            if (gm + 8 < M)
                *(float2*)(C + (size_t)(gm + 8) * N + gn) =
                    make_float2(acc[mi][ni][2] + b0v, acc[mi][ni][3] + b1v);
        }
    }
}

// ------------- q: LayerNorm(eps 1e-6) + RoPE (remapped per-token pos) ------
__global__ __launch_bounds__(256) void ln_rope_q(const float* __restrict__ xmap,
                                                 const float* __restrict__ gamma,
                                                 const float* __restrict__ beta) {
    int gw   = blockIdx.x * 8 + (threadIdx.x >> 5);
    int lane = threadIdx.x & 31;
    int r = gw / NH;                      // token = b*SEQ + s
    int h = gw - r * NH;
    float* row = g_Q + (size_t)r * DIMC + h * HDIM;
    float4 v = *(float4*)(row + lane * 4);

    float s  = v.x + v.y + v.z + v.w;
    float sq = v.x * v.x + v.y * v.y + v.z * v.z + v.w * v.w;
    #pragma unroll
    for (int o = 16; o; o >>= 1) {
        s  += __shfl_xor_sync(0xffffffffu, s,  o);
        sq += __shfl_xor_sync(0xffffffffu, sq, o);
    }
    float mean = s * (1.f / HDIM);
    float var  = sq * (1.f / HDIM) - mean * mean;
    float rs   = rsqrtf(var + 1e-6f);

    float4 gg = *(const float4*)(gamma + lane * 4);
    float4 bb = *(const float4*)(beta  + lane * 4);
    v.x = (v.x - mean) * rs * gg.x + bb.x;
    v.y = (v.y - mean) * rs * gg.y + bb.y;
    v.z = (v.z - mean) * rs * gg.z + bb.z;
    v.w = (v.w - mean) * rs * gg.w + bb.w;

    // flat-reshape semantics: [21,24,1024,HD] -> [1,24,21504,HD]
    int b = r >> 10, sidx = r & 1023;
    int l = (b * (NH * SEQ) + h * SEQ + sidx) % NTOK;
    float m0 = xmap[l], m1 = xmap[NTOK + l];
    float mn0 = g_minmax[0], mx0 = g_minmax[1], mn1 = g_minmax[2], mx1 = g_minmax[3];
    float pos = (m0 >= m1) ? (m0 - mn0) / (mx0 - mn0) * 4.0f
                           : (m1 - mn1) / (mx1 - mn1) * 4.0f + 20.0f;

    const float CF = -0.20762050593046868f;   // -2*log2(10000)/128
    int i0 = lane * 2;
    float f0 = exp2f((float)i0 * CF);
    float f1 = exp2f((float)(i0 + 1) * CF);
    float s0, c0, s1, c1;
    sincosf(pos * f0, &s0, &c0);
    sincosf(pos * f1, &s1, &c1);
    float4 o;
    o.x = v.x * c0 - v.y * s0;
    o.y = v.y * c0 + v.x * s0;
    o.z = v.z * c1 - v.w * s1;
    o.w = v.w * c1 + v.z * s1;
    *(float4*)(row + lane * 4) = o;
}

// ------------- k: LayerNorm(eps 1e-5) + RoPE (pos = 2 or 22) ---------------
__global__ __launch_bounds__(256) void k_ln_rope(const float* __restrict__ gamma,
                                                 const float* __restrict__ beta) {
    int gw   = blockIdx.x * 8 + (threadIdx.x >> 5);
    int lane = threadIdx.x & 31;
    int r = gw / NH;                      // encoder row = frame*NAK + na
    int h = gw - r * NH;
    float* row = g_KV + (size_t)r * (2 * DIMC) + h * HDIM;   // K half
    float4 v = *(float4*)(row + lane * 4);

    float s  = v.x + v.y + v.z + v.w;
    float sq = v.x * v.x + v.y * v.y + v.z * v.z + v.w * v.w;
    #pragma unroll
    for (int o = 16; o; o >>= 1) {
        s  += __shfl_xor_sync(0xffffffffu, s,  o);
        sq += __shfl_xor_sync(0xffffffffu, sq, o);
    }
    float mean = s * (1.f / HDIM);
    float var  = sq * (1.f / HDIM) - mean * mean;
    float rs   = rsqrtf(var + 1e-5f);

    float4 gg = *(const float4*)(gamma + lane * 4);
    float4 bb = *(const float4*)(beta  + lane * 4);
    v.x = (v.x - mean) * rs * gg.x + bb.x;
    v.y = (v.y - mean) * rs * gg.y + bb.y;
    v.z = (v.z - mean) * rs * gg.z + bb.z;
    v.w = (v.w - mean) * rs * gg.w + bb.w;

    int na = r & (NAK - 1);
    float pos = (na < NAK / 2) ? 2.0f : 22.0f;

    const float CF = -0.20762050593046868f;
    int i0 = lane * 2;
    float f0 = exp2f((float)i0 * CF);
    float f1 = exp2f((float)(i0 + 1) * CF);
    float s0, c0, s1, c1;
    sincosf(pos * f0, &s0, &c0);
    sincosf(pos * f1, &s1, &c1);
    float4 o;
    o.x = v.x * c0 - v.y * s0;
    o.y = v.y * c0 + v.x * s0;
    o.z = v.z * c1 - v.w * s1;
    o.w = v.w * c1 + v.z * s1;
    *(float4*)(row + lane * 4) = o;
}

// ------------- attention: per (b,h), NA=32 keys, softmax over lanes --------
#define VPAD 132
__global__ __launch_bounds__(256) void attn_kernel() {
    int bh = blockIdx.x;
    int b = bh / NH, h = bh - b * NH;
    __shared__ float ks[NAK][VPAD], vs[NAK][VPAD];
    int tid = threadIdx.x;
    for (int idx = tid; idx < NAK * HDIM; idx += 256) {
        int n = idx >> 7, d = idx & 127;
        size_t base = (size_t)(b * NAK + n) * (2 * DIMC) + h * HDIM + d;
        ks[n][d] = g_KV[base];
        vs[n][d] = g_KV[base + DIMC];
    }
    __syncthreads();

    int warp = tid >> 5, lane = tid & 31;
    const float SC = 0.08838834764831845f;   // 128^-0.5
    for (int s = warp; s < SEQ; s += 8) {
        const float* q = g_Q + (size_t)(b * SEQ + s) * DIMC + h * HDIM;
        float sc = 0.f;
        #pragma unroll
        for (int d = 0; d < HDIM; d += 4) {
            float4 qv = *(const float4*)(q + d);      // uniform across warp
            float4 kv = *(const float4*)(&ks[lane][d]);
            sc += qv.x * kv.x + qv.y * kv.y + qv.z * kv.z + qv.w * kv.w;
        }
        sc *= SC;
        float mx = sc;
        #pragma unroll
        for (int o = 16; o; o >>= 1) mx = fmaxf(mx, __shfl_xor_sync(0xffffffffu, mx, o));
        float e = __expf(sc - mx);
        float sum = e;
        #pragma unroll
        for (int o = 16; o; o >>= 1) sum += __shfl_xor_sync(0xffffffffu, sum, o);
        float p = e / sum;

        float4 acc = make_float4(0.f, 0.f, 0.f, 0.f);
        #pragma unroll
        for (int n = 0; n < NAK; n++) {
            float pn = __shfl_sync(0xffffffffu, p, n);
            float4 vv = *(const float4*)(&vs[n][lane * 4]);
            acc.x += pn * vv.x; acc.y += pn * vv.y;
            acc.z += pn * vv.z; acc.w += pn * vv.w;
        }
        *(float4*)(g_O + (size_t)(b * SEQ + s) * DIMC + h * HDIM + lane * 4) = acc;
    }
}

extern "C" void kernel_launch(void* const* d_in, const int* in_sizes, int n_in,
                              void* d_out, int out_size) {
    const float* x     = (const float*)d_in[0];
    const float* enc   = (const float*)d_in[1];
    const float* xmap  = (const float*)d_in[2];
    const float* q_w   = (const float*)d_in[3];
    const float* q_b   = (const float*)d_in[4];
    const float* kv_w  = (const float*)d_in[5];
    const float* kv_b  = (const float*)d_in[6];
    const float* prj_w = (const float*)d_in[7];
    const float* prj_b = (const float*)d_in[8];
    const float* qn_g  = (const float*)d_in[9];
    const float* qn_b  = (const float*)d_in[10];
    const float* kn_g  = (const float*)d_in[11];
    const float* kn_b  = (const float*)d_in[12];
    float* out = (float*)d_out;

    float *Q, *O, *KV;
    cudaGetSymbolAddress((void**)&Q,  g_Q);
    cudaGetSymbolAddress((void**)&O,  g_O);
    cudaGetSymbolAddress((void**)&KV, g_KV);

    minmax_kernel<<<2, 256>>>(xmap);

    dim3 gq(DIMC / BN, (NTOK + BM - 1) / BM);
    gemm_split_bf16<<<gq, 256>>>(x, q_w, q_b, Q, NTOK, DIMC, DIMC);

    dim3 gkv((2 * DIMC) / BN, (ENCR + BM - 1) / BM);
    gemm_split_bf16<<<gkv, 256>>>(enc, kv_w, kv_b, KV, ENCR, 2 * DIMC, ENCC);

    ln_rope_q<<<(NTOK * NH) / 8, 256>>>(xmap, qn_g, qn_b);
    k_ln_rope<<<(ENCR * NH) / 8, 256>>>(kn_g, kn_b);

    attn_kernel<<<N_T * NH, 256>>>();

    dim3 gp(DIMC / BN, (NTOK + BM - 1) / BM);
    gemm_split_bf16<<<gp, 256>>>(O, prj_w, prj_b, out, NTOK, DIMC, DIMC);
}

// round 7
// speedup vs baseline: 1.3465x; 1.3465x over previous
#include <cuda_runtime.h>
#include <cuda_fp16.h>
#include <cstdint>

#define N_T   21
#define SEQ   1024
#define DIMC  3072
#define NH    24
#define HDIM  128
#define ENCC  768
#define NAK   32
#define NTOK  (N_T * SEQ)          /* 21504 */
#define ENCR  (N_T * NAK)          /* 672 */

// ---------------- scratch (device globals: allocation-free) ----------------
__device__ float g_Q [(size_t)NTOK * DIMC];
__device__ float g_O [(size_t)NTOK * DIMC];
__device__ float g_KV[(size_t)ENCR * 2 * DIMC];
__device__ float g_minmax[4];

__device__ __half g_xh [(size_t)NTOK * DIMC];      // activations, single fp16
__device__ __half g_oh [(size_t)NTOK * DIMC];
__device__ __half g_eh [(size_t)ENCR * ENCC];
__device__ __half g_wqh[(size_t)DIMC * DIMC];      // weights, fp16 hi/lo split
__device__ __half g_wql[(size_t)DIMC * DIMC];
__device__ __half g_wph[(size_t)DIMC * DIMC];
__device__ __half g_wpl[(size_t)DIMC * DIMC];
__device__ __half g_wkh[(size_t)2 * DIMC * ENCC];
__device__ __half g_wkl[(size_t)2 * DIMC * ENCC];

// ---------------- conversions ----------------------------------------------
__global__ __launch_bounds__(256) void convert_single_h(
    const float4* __restrict__ in, __half2* __restrict__ out, int n4)
{
    int i = blockIdx.x * 256 + threadIdx.x;
    if (i >= n4) return;
    float4 v = in[i];
    out[2 * i]     = __floats2half2_rn(v.x, v.y);
    out[2 * i + 1] = __floats2half2_rn(v.z, v.w);
}

__global__ __launch_bounds__(256) void convert_pair_h(
    const float4* __restrict__ in, __half2* __restrict__ hi,
    __half2* __restrict__ lo, int n4)
{
    int i = blockIdx.x * 256 + threadIdx.x;
    if (i >= n4) return;
    float4 v = in[i];
    __half hx = __float2half_rn(v.x), hy = __float2half_rn(v.y);
    __half hz = __float2half_rn(v.z), hw = __float2half_rn(v.w);
    hi[2 * i]     = __half2(hx, hy);
    hi[2 * i + 1] = __half2(hz, hw);
    lo[2 * i]     = __floats2half2_rn(v.x - __half2float(hx), v.y - __half2float(hy));
    lo[2 * i + 1] = __floats2half2_rn(v.z - __half2float(hz), v.w - __half2float(hw));
}

// ---------------- fp16 2-term GEMM: C = A[M,K] @ (Bh+Bl)[N,K]^T + bias -----
// 128x128 tile, BK=32, 3-stage cp.async pipeline, mma.sync.m16n8k16.f16.
#define ROWB   80                      /* bytes per smem row: 64 data + 16 pad */
#define ARRB   (128 * ROWB)            /* 10240 B per operand array            */
#define OFF_A  0
#define OFF_BH ARRB
#define OFF_BL (2 * ARRB)
#define STAGEB (3 * ARRB)              /* 30720 B per stage                    */
#define GEMM_SMEM (3 * STAGEB)         /* 92160 B                              */

__device__ __forceinline__ uint32_t smem_u32(const void* p) {
    uint32_t a;
    asm("{ .reg .u64 t; cvta.to.shared.u64 t, %1; cvt.u32.u64 %0, t; }" : "=r"(a) : "l"(p));
    return a;
}

__device__ __forceinline__ void cp16(uint32_t dst, const void* src, unsigned bytes) {
    asm volatile("cp.async.cg.shared.global [%0], [%1], 16, %2;"
                 :: "r"(dst), "l"(src), "r"(bytes) : "memory");
}

__device__ __forceinline__ void mma_f16(float* c, const unsigned* a, unsigned b0, unsigned b1) {
    asm volatile(
        "mma.sync.aligned.m16n8k16.row.col.f32.f16.f16.f32 "
        "{%0,%1,%2,%3}, {%4,%5,%6,%7}, {%8,%9}, {%0,%1,%2,%3};\n"
        : "+f"(c[0]), "+f"(c[1]), "+f"(c[2]), "+f"(c[3])
        : "r"(a[0]), "r"(a[1]), "r"(a[2]), "r"(a[3]), "r"(b0), "r"(b1));
}

__global__ __launch_bounds__(256) void gemm_fp16x2(
    const __half* __restrict__ A, const __half* __restrict__ Bh,
    const __half* __restrict__ Bl, const float* __restrict__ bias,
    float* __restrict__ C, int M, int N, int K)
{
    extern __shared__ __align__(128) char smem[];
    uint32_t sb = smem_u32(smem);

    int tid  = threadIdx.x;
    int warp = tid >> 5, lane = tid & 31;
    int wm = warp >> 1, wn = warp & 1;           // 4x2 warps; warp tile 32x64
    int quad = lane >> 2, t4 = lane & 3;
    int m0 = blockIdx.y * 128, n0 = blockIdx.x * 128;
    int nk = K >> 5;

    float acc[2][8][4];
    #pragma unroll
    for (int i = 0; i < 2; i++)
        #pragma unroll
        for (int j = 0; j < 8; j++)
            #pragma unroll
            for (int c = 0; c < 4; c++) acc[i][j][c] = 0.f;

    auto issue_stage = [&](int kc) {
        int slot = kc % 3;
        uint32_t stb = sb + slot * STAGEB;
        int kx = kc * 32;
        #pragma unroll
        for (int j = 0; j < 2; j++) {
            int chunk = tid * 2 + j;             // 0..511
            int row = chunk >> 2, kcx = chunk & 3;
            uint32_t doff = row * ROWB + kcx * 16;
            // A (rows may be OOB for M=672 case)
            int gm = m0 + row;
            int gmc = gm < M ? gm : M - 1;
            cp16(stb + OFF_A + doff, A + (size_t)gmc * K + kx + kcx * 8,
                 gm < M ? 16u : 0u);
            // Bh / Bl (N always multiple of 128)
            size_t boff = (size_t)(n0 + row) * K + kx + kcx * 8;
            cp16(stb + OFF_BH + doff, Bh + boff, 16u);
            cp16(stb + OFF_BL + doff, Bl + boff, 16u);
        }
    };

    issue_stage(0);
    asm volatile("cp.async.commit_group;" ::: "memory");
    issue_stage(1);
    asm volatile("cp.async.commit_group;" ::: "memory");

    for (int kc = 0; kc < nk; kc++) {
        asm volatile("cp.async.wait_group 1;" ::: "memory");
        __syncthreads();
        if (kc + 2 < nk) issue_stage(kc + 2);
        asm volatile("cp.async.commit_group;" ::: "memory");

        int slot = kc % 3;
        const unsigned* pA  = (const unsigned*)(smem + slot * STAGEB + OFF_A);
        const unsigned* pBh = (const unsigned*)(smem + slot * STAGEB + OFF_BH);
        const unsigned* pBl = (const unsigned*)(smem + slot * STAGEB + OFF_BL);

        #pragma unroll
        for (int ks = 0; ks < 2; ks++) {
            int kb = ks * 8;
            unsigned a[2][4];
            #pragma unroll
            for (int mi = 0; mi < 2; mi++) {
                int r = wm * 32 + mi * 16;
                a[mi][0] = pA[(r + quad    ) * 20 + kb + t4];
                a[mi][1] = pA[(r + quad + 8) * 20 + kb + t4];
                a[mi][2] = pA[(r + quad    ) * 20 + kb + t4 + 4];
                a[mi][3] = pA[(r + quad + 8) * 20 + kb + t4 + 4];
            }
            #pragma unroll
            for (int ni = 0; ni < 8; ni++) {
                int cb = wn * 64 + ni * 8;
                unsigned bh0 = pBh[(cb + quad) * 20 + kb + t4];
                unsigned bh1 = pBh[(cb + quad) * 20 + kb + t4 + 4];
                unsigned bl0 = pBl[(cb + quad) * 20 + kb + t4];
                unsigned bl1 = pBl[(cb + quad) * 20 + kb + t4 + 4];
                #pragma unroll
                for (int mi = 0; mi < 2; mi++) {
                    mma_f16(acc[mi][ni], a[mi], bh0, bh1);
                    mma_f16(acc[mi][ni], a[mi], bl0, bl1);
                }
            }
        }
    }

    #pragma unroll
    for (int mi = 0; mi < 2; mi++) {
        int gm = m0 + wm * 32 + mi * 16 + quad;
        #pragma unroll
        for (int ni = 0; ni < 8; ni++) {
            int gn = n0 + wn * 64 + ni * 8 + t4 * 2;
            float b0v = bias[gn], b1v = bias[gn + 1];
            if (gm < M)
                *(float2*)(C + (size_t)gm * N + gn) =
                    make_float2(acc[mi][ni][0] + b0v, acc[mi][ni][1] + b1v);
            if (gm + 8 < M)
                *(float2*)(C + (size_t)(gm + 8) * N + gn) =
                    make_float2(acc[mi][ni][2] + b0v, acc[mi][ni][3] + b1v);
        }
    }
}

// ---------------- min/max of the two x_ref_attn_map rows -------------------
__global__ void minmax_kernel(const float* __restrict__ xmap) {
    int row = blockIdx.x;
    const float* p = xmap + row * NTOK;
    float mn = 3.4e38f, mx = -3.4e38f;
    for (int i = threadIdx.x; i < NTOK; i += blockDim.x) {
        float v = p[i];
        mn = fminf(mn, v); mx = fmaxf(mx, v);
    }
    __shared__ float smn[32], smx[32];
    int lane = threadIdx.x & 31, w = threadIdx.x >> 5;
    #pragma unroll
    for (int o = 16; o; o >>= 1) {
        mn = fminf(mn, __shfl_xor_sync(0xffffffffu, mn, o));
        mx = fmaxf(mx, __shfl_xor_sync(0xffffffffu, mx, o));
    }
    if (lane == 0) { smn[w] = mn; smx[w] = mx; }
    __syncthreads();
    if (w == 0) {
        int nw = blockDim.x >> 5;
        mn = (lane < nw) ? smn[lane] :  3.4e38f;
        mx = (lane < nw) ? smx[lane] : -3.4e38f;
        #pragma unroll
        for (int o = 16; o; o >>= 1) {
            mn = fminf(mn, __shfl_xor_sync(0xffffffffu, mn, o));
            mx = fmaxf(mx, __shfl_xor_sync(0xffffffffu, mx, o));
        }
        if (lane == 0) { g_minmax[row * 2] = mn; g_minmax[row * 2 + 1] = mx; }
    }
}

// ------------- q: LayerNorm(eps 1e-6) + RoPE (remapped per-token pos) ------
__global__ __launch_bounds__(256) void ln_rope_q(const float* __restrict__ xmap,
                                                 const float* __restrict__ gamma,
                                                 const float* __restrict__ beta) {
    int gw   = blockIdx.x * 8 + (threadIdx.x >> 5);
    int lane = threadIdx.x & 31;
    int r = gw / NH;
    int h = gw - r * NH;
    float* row = g_Q + (size_t)r * DIMC + h * HDIM;
    float4 v = *(float4*)(row + lane * 4);

    float s  = v.x + v.y + v.z + v.w;
    float sq = v.x * v.x + v.y * v.y + v.z * v.z + v.w * v.w;
    #pragma unroll
    for (int o = 16; o; o >>= 1) {
        s  += __shfl_xor_sync(0xffffffffu, s,  o);
        sq += __shfl_xor_sync(0xffffffffu, sq, o);
    }
    float mean = s * (1.f / HDIM);
    float var  = sq * (1.f / HDIM) - mean * mean;
    float rs   = rsqrtf(var + 1e-6f);

    float4 gg = *(const float4*)(gamma + lane * 4);
    float4 bb = *(const float4*)(beta  + lane * 4);
    v.x = (v.x - mean) * rs * gg.x + bb.x;
    v.y = (v.y - mean) * rs * gg.y + bb.y;
    v.z = (v.z - mean) * rs * gg.z + bb.z;
    v.w = (v.w - mean) * rs * gg.w + bb.w;

    int b = r >> 10, sidx = r & 1023;
    int l = (b * (NH * SEQ) + h * SEQ + sidx) % NTOK;
    float m0 = xmap[l], m1 = xmap[NTOK + l];
    float mn0 = g_minmax[0], mx0 = g_minmax[1], mn1 = g_minmax[2], mx1 = g_minmax[3];
    float pos = (m0 >= m1) ? (m0 - mn0) / (mx0 - mn0) * 4.0f
                           : (m1 - mn1) / (mx1 - mn1) * 4.0f + 20.0f;

    const float CF = -0.20762050593046868f;   // -2*log2(10000)/128
    int i0 = lane * 2;
    float f0 = exp2f((float)i0 * CF);
    float f1 = exp2f((float)(i0 + 1) * CF);
    float s0, c0, s1, c1;
    sincosf(pos * f0, &s0, &c0);
    sincosf(pos * f1, &s1, &c1);
    float4 o;
    o.x = v.x * c0 - v.y * s0;
    o.y = v.y * c0 + v.x * s0;
    o.z = v.z * c1 - v.w * s1;
    o.w = v.w * c1 + v.z * s1;
    *(float4*)(row + lane * 4) = o;
}

// ------------- k: LayerNorm(eps 1e-5) + RoPE (pos = 2 or 22) ---------------
__global__ __launch_bounds__(256) void k_ln_rope(const float* __restrict__ gamma,
                                                 const float* __restrict__ beta) {
    int gw   = blockIdx.x * 8 + (threadIdx.x >> 5);
    int lane = threadIdx.x & 31;
    int r = gw / NH;
    int h = gw - r * NH;
    float* row = g_KV + (size_t)r * (2 * DIMC) + h * HDIM;
    float4 v = *(float4*)(row + lane * 4);

    float s  = v.x + v.y + v.z + v.w;
    float sq = v.x * v.x + v.y * v.y + v.z * v.z + v.w * v.w;
    #pragma unroll
    for (int o = 16; o; o >>= 1) {
        s  += __shfl_xor_sync(0xffffffffu, s,  o);
        sq += __shfl_xor_sync(0xffffffffu, sq, o);
    }
    float mean = s * (1.f / HDIM);
    float var  = sq * (1.f / HDIM) - mean * mean;
    float rs   = rsqrtf(var + 1e-5f);

    float4 gg = *(const float4*)(gamma + lane * 4);
    float4 bb = *(const float4*)(beta  + lane * 4);
    v.x = (v.x - mean) * rs * gg.x + bb.x;
    v.y = (v.y - mean) * rs * gg.y + bb.y;
    v.z = (v.z - mean) * rs * gg.z + bb.z;
    v.w = (v.w - mean) * rs * gg.w + bb.w;

    int na = r & (NAK - 1);
    float pos = (na < NAK / 2) ? 2.0f : 22.0f;

    const float CF = -0.20762050593046868f;
    int i0 = lane * 2;
    float f0 = exp2f((float)i0 * CF);
    float f1 = exp2f((float)(i0 + 1) * CF);
    float s0, c0, s1, c1;
    sincosf(pos * f0, &s0, &c0);
    sincosf(pos * f1, &s1, &c1);
    float4 o;
    o.x = v.x * c0 - v.y * s0;
    o.y = v.y * c0 + v.x * s0;
    o.z = v.z * c1 - v.w * s1;
    o.w = v.w * c1 + v.z * s1;
    *(float4*)(row + lane * 4) = o;
}

// ------------- attention: per (b,h), NA=32 keys ----------------------------
#define VPAD 132
__global__ __launch_bounds__(256) void attn_kernel() {
    int bh = blockIdx.x;
    int b = bh / NH, h = bh - b * NH;
    __shared__ float ks[NAK][VPAD], vs[NAK][VPAD];
    int tid = threadIdx.x;
    for (int idx = tid; idx < NAK * HDIM; idx += 256) {
        int n = idx >> 7, d = idx & 127;
        size_t base = (size_t)(b * NAK + n) * (2 * DIMC) + h * HDIM + d;
        ks[n][d] = g_KV[base];
        vs[n][d] = g_KV[base + DIMC];
    }
    __syncthreads();

    int warp = tid >> 5, lane = tid & 31;
    const float SC = 0.08838834764831845f;
    for (int s = warp; s < SEQ; s += 8) {
        const float* q = g_Q + (size_t)(b * SEQ + s) * DIMC + h * HDIM;
        float sc = 0.f;
        #pragma unroll
        for (int d = 0; d < HDIM; d += 4) {
            float4 qv = *(const float4*)(q + d);
            float4 kv = *(const float4*)(&ks[lane][d]);
            sc += qv.x * kv.x + qv.y * kv.y + qv.z * kv.z + qv.w * kv.w;
        }
        sc *= SC;
        float mx = sc;
        #pragma unroll
        for (int o = 16; o; o >>= 1) mx = fmaxf(mx, __shfl_xor_sync(0xffffffffu, mx, o));
        float e = __expf(sc - mx);
        float sum = e;
        #pragma unroll
        for (int o = 16; o; o >>= 1) sum += __shfl_xor_sync(0xffffffffu, sum, o);
        float p = e / sum;

        float4 acc = make_float4(0.f, 0.f, 0.f, 0.f);
        #pragma unroll
        for (int n = 0; n < NAK; n++) {
            float pn = __shfl_sync(0xffffffffu, p, n);
            float4 vv = *(const float4*)(&vs[n][lane * 4]);
            acc.x += pn * vv.x; acc.y += pn * vv.y;
            acc.z += pn * vv.z; acc.w += pn * vv.w;
        }
        *(float4*)(g_O + (size_t)(b * SEQ + s) * DIMC + h * HDIM + lane * 4) = acc;
    }
}

// ======================= host side =======================
static void conv1(const float* in, __half* out, size_t n) {
    int n4 = (int)(n / 4);
    convert_single_h<<<(n4 + 255) / 256, 256>>>((const float4*)in, (__half2*)out, n4);
}
static void conv2(const float* in, __half* hi, __half* lo, size_t n) {
    int n4 = (int)(n / 4);
    convert_pair_h<<<(n4 + 255) / 256, 256>>>((const float4*)in, (__half2*)hi, (__half2*)lo, n4);
}

extern "C" void kernel_launch(void* const* d_in, const int* in_sizes, int n_in,
                              void* d_out, int out_size) {
    const float* x     = (const float*)d_in[0];
    const float* enc_i = (const float*)d_in[1];
    const float* xmap  = (const float*)d_in[2];
    const float* q_w   = (const float*)d_in[3];
    const float* q_b   = (const float*)d_in[4];
    const float* kv_w  = (const float*)d_in[5];
    const float* kv_b  = (const float*)d_in[6];
    const float* prj_w = (const float*)d_in[7];
    const float* prj_b = (const float*)d_in[8];
    const float* qn_g  = (const float*)d_in[9];
    const float* qn_b  = (const float*)d_in[10];
    const float* kn_g  = (const float*)d_in[11];
    const float* kn_b  = (const float*)d_in[12];
    float* out = (float*)d_out;

    float *Q, *O, *KV;
    __half *xh, *oh, *eh, *wqh, *wql, *wph, *wpl, *wkh, *wkl;
    cudaGetSymbolAddress((void**)&Q,   g_Q);
    cudaGetSymbolAddress((void**)&O,   g_O);
    cudaGetSymbolAddress((void**)&KV,  g_KV);
    cudaGetSymbolAddress((void**)&xh,  g_xh);
    cudaGetSymbolAddress((void**)&oh,  g_oh);
    cudaGetSymbolAddress((void**)&eh,  g_eh);
    cudaGetSymbolAddress((void**)&wqh, g_wqh); cudaGetSymbolAddress((void**)&wql, g_wql);
    cudaGetSymbolAddress((void**)&wph, g_wph); cudaGetSymbolAddress((void**)&wpl, g_wpl);
    cudaGetSymbolAddress((void**)&wkh, g_wkh); cudaGetSymbolAddress((void**)&wkl, g_wkl);

    cudaFuncSetAttribute(gemm_fp16x2, cudaFuncAttributeMaxDynamicSharedMemorySize, GEMM_SMEM);

    minmax_kernel<<<2, 256>>>(xmap);

    conv1(x,     xh,  (size_t)NTOK * DIMC);
    conv1(enc_i, eh,  (size_t)ENCR * ENCC);
    conv2(q_w,   wqh, wql, (size_t)DIMC * DIMC);
    conv2(kv_w,  wkh, wkl, (size_t)2 * DIMC * ENCC);
    conv2(prj_w, wph, wpl, (size_t)DIMC * DIMC);

    // GEMM 1: Q = x @ q_w^T   [21504 x 3072] x [3072 x 3072]
    gemm_fp16x2<<<dim3(DIMC / 128, NTOK / 128), 256, GEMM_SMEM>>>(
        xh, wqh, wql, q_b, Q, NTOK, DIMC, DIMC);

    // GEMM 2: KV = enc @ kv_w^T   [672 x 768] x [6144 x 768]
    gemm_fp16x2<<<dim3((2 * DIMC) / 128, (ENCR + 127) / 128), 256, GEMM_SMEM>>>(
        eh, wkh, wkl, kv_b, KV, ENCR, 2 * DIMC, ENCC);

    ln_rope_q<<<(NTOK * NH) / 8, 256>>>(xmap, qn_g, qn_b);
    k_ln_rope<<<(ENCR * NH) / 8, 256>>>(kn_g, kn_b);

    attn_kernel<<<N_T * NH, 256>>>();

    conv1(O, oh, (size_t)NTOK * DIMC);

    // GEMM 3: out = O @ prj_w^T
    gemm_fp16x2<<<dim3(DIMC / 128, NTOK / 128), 256, GEMM_SMEM>>>(
        oh, wph, wpl, prj_b, out, NTOK, DIMC, DIMC);
}

// round 9
// speedup vs baseline: 1.9264x; 1.4307x over previous
#include <cuda_runtime.h>
#include <cuda_fp16.h>
#include <cstdint>

#define N_T   21
#define SEQ   1024
#define DIMC  3072
#define NH    24
#define HDIM  128
#define ENCC  768
#define NAK   32
#define NTOK  (N_T * SEQ)          /* 21504 */
#define ENCR  (N_T * NAK)          /* 672 */

// ---------------- scratch (device globals: allocation-free) ----------------
__device__ float g_Q [(size_t)NTOK * DIMC];
__device__ float g_KV[(size_t)ENCR * 2 * DIMC];
__device__ float g_minmax[4];

__device__ __half g_xh [(size_t)NTOK * DIMC];      // activations fp16
__device__ __half g_oh [(size_t)NTOK * DIMC];      // attn output fp16
__device__ __half g_eh [(size_t)ENCR * ENCC];
__device__ __half g_wqh[(size_t)DIMC * DIMC];      // weights fp16 (single)
__device__ __half g_wph[(size_t)DIMC * DIMC];
__device__ __half g_wkh[(size_t)2 * DIMC * ENCC];

// ---------------- conversions ----------------------------------------------
__global__ __launch_bounds__(256) void convert_single_h(
    const float4* __restrict__ in, __half2* __restrict__ out, int n4)
{
    int i = blockIdx.x * 256 + threadIdx.x;
    if (i >= n4) return;
    float4 v = in[i];
    out[2 * i]     = __floats2half2_rn(v.x, v.y);
    out[2 * i + 1] = __floats2half2_rn(v.z, v.w);
}

// ---------------- fp16 GEMM: C = A[M,K] @ B[N,K]^T + bias ------------------
// 128x128 tile, BK=32, 3-stage cp.async pipeline, mma.sync.m16n8k16.f16.
#define ROWB   80                      /* bytes per smem row: 64 data + 16 pad */
#define ARRB   (128 * ROWB)            /* 10240 B per operand array            */
#define OFF_A  0
#define OFF_B  ARRB
#define STAGEB (2 * ARRB)              /* 20480 B per stage                    */
#define GEMM_SMEM (3 * STAGEB)         /* 61440 B                              */

__device__ __forceinline__ uint32_t smem_u32(const void* p) {
    uint32_t a;
    asm("{ .reg .u64 t; cvta.to.shared.u64 t, %1; cvt.u32.u64 %0, t; }" : "=r"(a) : "l"(p));
    return a;
}

__device__ __forceinline__ void cp16(uint32_t dst, const void* src, unsigned bytes) {
    asm volatile("cp.async.cg.shared.global [%0], [%1], 16, %2;"
                 :: "r"(dst), "l"(src), "r"(bytes) : "memory");
}

__device__ __forceinline__ void mma_f16(float* c, const unsigned* a, unsigned b0, unsigned b1) {
    asm volatile(
        "mma.sync.aligned.m16n8k16.row.col.f32.f16.f16.f32 "
        "{%0,%1,%2,%3}, {%4,%5,%6,%7}, {%8,%9}, {%0,%1,%2,%3};\n"
        : "+f"(c[0]), "+f"(c[1]), "+f"(c[2]), "+f"(c[3])
        : "r"(a[0]), "r"(a[1]), "r"(a[2]), "r"(a[3]), "r"(b0), "r"(b1));
}

__global__ __launch_bounds__(256) void gemm_fp16(
    const __half* __restrict__ A, const __half* __restrict__ B,
    const float* __restrict__ bias, float* __restrict__ C,
    int M, int N, int K)
{
    extern __shared__ __align__(128) char smem[];
    uint32_t sb = smem_u32(smem);

    int tid  = threadIdx.x;
    int warp = tid >> 5, lane = tid & 31;
    int wm = warp >> 1, wn = warp & 1;           // 4x2 warps; warp tile 32x64
    int quad = lane >> 2, t4 = lane & 3;
    int m0 = blockIdx.y * 128, n0 = blockIdx.x * 128;
    int nk = K >> 5;

    float acc[2][8][4];
    #pragma unroll
    for (int i = 0; i < 2; i++)
        #pragma unroll
        for (int j = 0; j < 8; j++)
            #pragma unroll
            for (int c = 0; c < 4; c++) acc[i][j][c] = 0.f;

    auto issue_stage = [&](int kc) {
        int slot = kc % 3;
        uint32_t stb = sb + slot * STAGEB;
        int kx = kc * 32;
        #pragma unroll
        for (int j = 0; j < 2; j++) {
            int chunk = tid * 2 + j;             // 0..511
            int row = chunk >> 2, kcx = chunk & 3;
            uint32_t doff = row * ROWB + kcx * 16;
            int gm = m0 + row;
            int gmc = gm < M ? gm : M - 1;
            cp16(stb + OFF_A + doff, A + (size_t)gmc * K + kx + kcx * 8,
                 gm < M ? 16u : 0u);
            cp16(stb + OFF_B + doff, B + (size_t)(n0 + row) * K + kx + kcx * 8, 16u);
        }
    };

    issue_stage(0);
    asm volatile("cp.async.commit_group;" ::: "memory");
    issue_stage(1);
    asm volatile("cp.async.commit_group;" ::: "memory");

    for (int kc = 0; kc < nk; kc++) {
        asm volatile("cp.async.wait_group 1;" ::: "memory");
        __syncthreads();
        if (kc + 2 < nk) issue_stage(kc + 2);
        asm volatile("cp.async.commit_group;" ::: "memory");

        int slot = kc % 3;
        const unsigned* pA = (const unsigned*)(smem + slot * STAGEB + OFF_A);
        const unsigned* pB = (const unsigned*)(smem + slot * STAGEB + OFF_B);

        #pragma unroll
        for (int ks = 0; ks < 2; ks++) {
            int kb = ks * 8;
            unsigned a[2][4];
            #pragma unroll
            for (int mi = 0; mi < 2; mi++) {
                int r = wm * 32 + mi * 16;
                a[mi][0] = pA[(r + quad    ) * 20 + kb + t4];
                a[mi][1] = pA[(r + quad + 8) * 20 + kb + t4];
                a[mi][2] = pA[(r + quad    ) * 20 + kb + t4 + 4];
                a[mi][3] = pA[(r + quad + 8) * 20 + kb + t4 + 4];
            }
            #pragma unroll
            for (int ni = 0; ni < 8; ni++) {
                int cb = wn * 64 + ni * 8;
                unsigned b0 = pB[(cb + quad) * 20 + kb + t4];
                unsigned b1 = pB[(cb + quad) * 20 + kb + t4 + 4];
                #pragma unroll
                for (int mi = 0; mi < 2; mi++)
                    mma_f16(acc[mi][ni], a[mi], b0, b1);
            }
        }
    }

    #pragma unroll
    for (int mi = 0; mi < 2; mi++) {
        int gm = m0 + wm * 32 + mi * 16 + quad;
        #pragma unroll
        for (int ni = 0; ni < 8; ni++) {
            int gn = n0 + wn * 64 + ni * 8 + t4 * 2;
            float b0v = bias[gn], b1v = bias[gn + 1];
            if (gm < M)
                *(float2*)(C + (size_t)gm * N + gn) =
                    make_float2(acc[mi][ni][0] + b0v, acc[mi][ni][1] + b1v);
            if (gm + 8 < M)
                *(float2*)(C + (size_t)(gm + 8) * N + gn) =
                    make_float2(acc[mi][ni][2] + b0v, acc[mi][ni][3] + b1v);
        }
    }
}

// ---------------- min/max of the two x_ref_attn_map rows -------------------
__global__ void minmax_kernel(const float* __restrict__ xmap) {
    int row = blockIdx.x;
    const float* p = xmap + row * NTOK;
    float mn = 3.4e38f, mx = -3.4e38f;
    for (int i = threadIdx.x; i < NTOK; i += blockDim.x) {
        float v = p[i];
        mn = fminf(mn, v); mx = fmaxf(mx, v);
    }
    __shared__ float smn[32], smx[32];
    int lane = threadIdx.x & 31, w = threadIdx.x >> 5;
    #pragma unroll
    for (int o = 16; o; o >>= 1) {
        mn = fminf(mn, __shfl_xor_sync(0xffffffffu, mn, o));
        mx = fmaxf(mx, __shfl_xor_sync(0xffffffffu, mx, o));
    }
    if (lane == 0) { smn[w] = mn; smx[w] = mx; }
    __syncthreads();
    if (w == 0) {
        int nw = blockDim.x >> 5;
        mn = (lane < nw) ? smn[lane] :  3.4e38f;
        mx = (lane < nw) ? smx[lane] : -3.4e38f;
        #pragma unroll
        for (int o = 16; o; o >>= 1) {
            mn = fminf(mn, __shfl_xor_sync(0xffffffffu, mn, o));
            mx = fmaxf(mx, __shfl_xor_sync(0xffffffffu, mx, o));
        }
        if (lane == 0) { g_minmax[row * 2] = mn; g_minmax[row * 2 + 1] = mx; }
    }
}

// ------------- q: LayerNorm(eps 1e-6) + RoPE (remapped per-token pos) ------
__global__ __launch_bounds__(256) void ln_rope_q(const float* __restrict__ xmap,
                                                 const float* __restrict__ gamma,
                                                 const float* __restrict__ beta) {
    int gw   = blockIdx.x * 8 + (threadIdx.x >> 5);
    int lane = threadIdx.x & 31;
    int r = gw / NH;
    int h = gw - r * NH;
    float* row = g_Q + (size_t)r * DIMC + h * HDIM;
    float4 v = *(float4*)(row + lane * 4);

    float s  = v.x + v.y + v.z + v.w;
    float sq = v.x * v.x + v.y * v.y + v.z * v.z + v.w * v.w;
    #pragma unroll
    for (int o = 16; o; o >>= 1) {
        s  += __shfl_xor_sync(0xffffffffu, s,  o);
        sq += __shfl_xor_sync(0xffffffffu, sq, o);
    }
    float mean = s * (1.f / HDIM);
    float var  = sq * (1.f / HDIM) - mean * mean;
    float rs   = rsqrtf(var + 1e-6f);

    float4 gg = *(const float4*)(gamma + lane * 4);
    float4 bb = *(const float4*)(beta  + lane * 4);
    v.x = (v.x - mean) * rs * gg.x + bb.x;
    v.y = (v.y - mean) * rs * gg.y + bb.y;
    v.z = (v.z - mean) * rs * gg.z + bb.z;
    v.w = (v.w - mean) * rs * gg.w + bb.w;

    int b = r >> 10, sidx = r & 1023;
    int l = (b * (NH * SEQ) + h * SEQ + sidx) % NTOK;
    float m0 = xmap[l], m1 = xmap[NTOK + l];
    float mn0 = g_minmax[0], mx0 = g_minmax[1], mn1 = g_minmax[2], mx1 = g_minmax[3];
    float pos = (m0 >= m1) ? (m0 - mn0) / (mx0 - mn0) * 4.0f
                           : (m1 - mn1) / (mx1 - mn1) * 4.0f + 20.0f;

    const float CF = -0.20762050593046868f;   // -2*log2(10000)/128
    int i0 = lane * 2;
    float f0 = exp2f((float)i0 * CF);
    float f1 = exp2f((float)(i0 + 1) * CF);
    float s0, c0, s1, c1;
    sincosf(pos * f0, &s0, &c0);
    sincosf(pos * f1, &s1, &c1);
    float4 o;
    o.x = v.x * c0 - v.y * s0;
    o.y = v.y * c0 + v.x * s0;
    o.z = v.z * c1 - v.w * s1;
    o.w = v.w * c1 + v.z * s1;
    *(float4*)(row + lane * 4) = o;
}

// ------------- k: LayerNorm(eps 1e-5) + RoPE (pos = 2 or 22) ---------------
__global__ __launch_bounds__(256) void k_ln_rope(const float* __restrict__ gamma,
                                                 const float* __restrict__ beta) {
    int gw   = blockIdx.x * 8 + (threadIdx.x >> 5);
    int lane = threadIdx.x & 31;
    int r = gw / NH;
    int h = gw - r * NH;
    float* row = g_KV + (size_t)r * (2 * DIMC) + h * HDIM;
    float4 v = *(float4*)(row + lane * 4);

    float s  = v.x + v.y + v.z + v.w;
    float sq = v.x * v.x + v.y * v.y + v.z * v.z + v.w * v.w;
    #pragma unroll
    for (int o = 16; o; o >>= 1) {
        s  += __shfl_xor_sync(0xffffffffu, s,  o);
        sq += __shfl_xor_sync(0xffffffffu, sq, o);
    }
    float mean = s * (1.f / HDIM);
    float var  = sq * (1.f / HDIM) - mean * mean;
    float rs   = rsqrtf(var + 1e-5f);

    float4 gg = *(const float4*)(gamma + lane * 4);
    float4 bb = *(const float4*)(beta  + lane * 4);
    v.x = (v.x - mean) * rs * gg.x + bb.x;
    v.y = (v.y - mean) * rs * gg.y + bb.y;
    v.z = (v.z - mean) * rs * gg.z + bb.z;
    v.w = (v.w - mean) * rs * gg.w + bb.w;

    int na = r & (NAK - 1);
    float pos = (na < NAK / 2) ? 2.0f : 22.0f;

    const float CF = -0.20762050593046868f;
    int i0 = lane * 2;
    float f0 = exp2f((float)i0 * CF);
    float f1 = exp2f((float)(i0 + 1) * CF);
    float s0, c0, s1, c1;
    sincosf(pos * f0, &s0, &c0);
    sincosf(pos * f1, &s1, &c1);
    float4 o;
    o.x = v.x * c0 - v.y * s0;
    o.y = v.y * c0 + v.x * s0;
    o.z = v.z * c1 - v.w * s1;
    o.w = v.w * c1 + v.z * s1;
    *(float4*)(row + lane * 4) = o;
}

// ------------- attention: per (b,h), NA=32 keys; fp16 output ---------------
#define VPAD 132
__global__ __launch_bounds__(256) void attn_kernel() {
    int bh = blockIdx.x;
    int b = bh / NH, h = bh - b * NH;
    __shared__ float ks[NAK][VPAD], vs[NAK][VPAD];
    int tid = threadIdx.x;
    for (int idx = tid; idx < NAK * HDIM; idx += 256) {
        int n = idx >> 7, d = idx & 127;
        size_t base = (size_t)(b * NAK + n) * (2 * DIMC) + h * HDIM + d;
        ks[n][d] = g_KV[base];
        vs[n][d] = g_KV[base + DIMC];
    }
    __syncthreads();

    int warp = tid >> 5, lane = tid & 31;
    const float SC = 0.08838834764831845f;
    for (int s = warp; s < SEQ; s += 8) {
        const float* q = g_Q + (size_t)(b * SEQ + s) * DIMC + h * HDIM;
        float sc = 0.f;
        #pragma unroll
        for (int d = 0; d < HDIM; d += 4) {
            float4 qv = *(const float4*)(q + d);
            float4 kv = *(const float4*)(&ks[lane][d]);
            sc += qv.x * kv.x + qv.y * kv.y + qv.z * kv.z + qv.w * kv.w;
        }
        sc *= SC;
        float mx = sc;
        #pragma unroll
        for (int o = 16; o; o >>= 1) mx = fmaxf(mx, __shfl_xor_sync(0xffffffffu, mx, o));
        float e = __expf(sc - mx);
        float sum = e;
        #pragma unroll
        for (int o = 16; o; o >>= 1) sum += __shfl_xor_sync(0xffffffffu, sum, o);
        float p = e / sum;

        float4 acc = make_float4(0.f, 0.f, 0.f, 0.f);
        #pragma unroll
        for (int n = 0; n < NAK; n++) {
            float pn = __shfl_sync(0xffffffffu, p, n);
            float4 vv = *(const float4*)(&vs[n][lane * 4]);
            acc.x += pn * vv.x; acc.y += pn * vv.y;
            acc.z += pn * vv.z; acc.w += pn * vv.w;
        }
        __half2* op = (__half2*)(g_oh + (size_t)(b * SEQ + s) * DIMC + h * HDIM + lane * 4);
        op[0] = __floats2half2_rn(acc.x, acc.y);
        op[1] = __floats2half2_rn(acc.z, acc.w);
    }
}

// ======================= host side =======================
static void conv1(const float* in, __half* out, size_t n) {
    int n4 = (int)(n / 4);
    convert_single_h<<<(n4 + 255) / 256, 256>>>((const float4*)in, (__half2*)out, n4);
}

extern "C" void kernel_launch(void* const* d_in, const int* in_sizes, int n_in,
                              void* d_out, int out_size) {
    const float* x     = (const float*)d_in[0];
    const float* enc_i = (const float*)d_in[1];
    const float* xmap  = (const float*)d_in[2];
    const float* q_w   = (const float*)d_in[3];
    const float* q_b   = (const float*)d_in[4];
    const float* kv_w  = (const float*)d_in[5];
    const float* kv_b  = (const float*)d_in[6];
    const float* prj_w = (const float*)d_in[7];
    const float* prj_b = (const float*)d_in[8];
    const float* qn_g  = (const float*)d_in[9];
    const float* qn_b  = (const float*)d_in[10];
    const float* kn_g  = (const float*)d_in[11];
    const float* kn_b  = (const float*)d_in[12];
    float* out = (float*)d_out;

    float *Q, *KV;
    __half *xh, *oh, *eh, *wqh, *wph, *wkh;
    cudaGetSymbolAddress((void**)&Q,   g_Q);
    cudaGetSymbolAddress((void**)&KV,  g_KV);
    cudaGetSymbolAddress((void**)&xh,  g_xh);
    cudaGetSymbolAddress((void**)&oh,  g_oh);
    cudaGetSymbolAddress((void**)&eh,  g_eh);
    cudaGetSymbolAddress((void**)&wqh, g_wqh);
    cudaGetSymbolAddress((void**)&wph, g_wph);
    cudaGetSymbolAddress((void**)&wkh, g_wkh);

    cudaFuncSetAttribute(gemm_fp16, cudaFuncAttributeMaxDynamicSharedMemorySize, GEMM_SMEM);

    minmax_kernel<<<2, 256>>>(xmap);

    conv1(x,     xh,  (size_t)NTOK * DIMC);
    conv1(enc_i, eh,  (size_t)ENCR * ENCC);
    conv1(q_w,   wqh, (size_t)DIMC * DIMC);
    conv1(kv_w,  wkh, (size_t)2 * DIMC * ENCC);
    conv1(prj_w, wph, (size_t)DIMC * DIMC);

    // GEMM 1: Q = x @ q_w^T   [21504 x 3072] x [3072 x 3072]
    gemm_fp16<<<dim3(DIMC / 128, NTOK / 128), 256, GEMM_SMEM>>>(
        xh, wqh, q_b, Q, NTOK, DIMC, DIMC);

    // GEMM 2: KV = enc @ kv_w^T   [672 x 768] x [6144 x 768]
    gemm_fp16<<<dim3((2 * DIMC) / 128, (ENCR + 127) / 128), 256, GEMM_SMEM>>>(
        eh, wkh, kv_b, KV, ENCR, 2 * DIMC, ENCC);

    ln_rope_q<<<(NTOK * NH) / 8, 256>>>(xmap, qn_g, qn_b);
    k_ln_rope<<<(ENCR * NH) / 8, 256>>>(kn_g, kn_b);

    attn_kernel<<<N_T * NH, 256>>>();

    // GEMM 3: out = attn_out @ prj_w^T
    gemm_fp16<<<dim3(DIMC / 128, NTOK / 128), 256, GEMM_SMEM>>>(
        oh, wph, prj_b, out, NTOK, DIMC, DIMC);
}

// round 10
// speedup vs baseline: 2.2566x; 1.1714x over previous
#include <cuda_runtime.h>
#include <cuda_fp16.h>
#include <cstdint>

#define N_T   21
#define SEQ   1024
#define DIMC  3072
#define NH    24
#define HDIM  128
#define ENCC  768
#define NAK   32
#define NTOK  (N_T * SEQ)          /* 21504 */
#define ENCR  (N_T * NAK)          /* 672 */

// ---------------- scratch (device globals: allocation-free) ----------------
__device__ float g_Q [(size_t)NTOK * DIMC];
__device__ float g_KV[(size_t)ENCR * 2 * DIMC];
__device__ float g_minmax[4];

__device__ __half g_xh [(size_t)NTOK * DIMC];      // activations fp16
__device__ __half g_oh [(size_t)NTOK * DIMC];      // attn output fp16
__device__ __half g_eh [(size_t)ENCR * ENCC];
__device__ __half g_wqh[(size_t)DIMC * DIMC];      // weights fp16
__device__ __half g_wph[(size_t)DIMC * DIMC];
__device__ __half g_wkh[(size_t)2 * DIMC * ENCC];

// ---------------- conversions ----------------------------------------------
__global__ __launch_bounds__(256) void convert_single_h(
    const float4* __restrict__ in, __half2* __restrict__ out, int n4)
{
    int i = blockIdx.x * 256 + threadIdx.x;
    if (i >= n4) return;
    float4 v = in[i];
    out[2 * i]     = __floats2half2_rn(v.x, v.y);
    out[2 * i + 1] = __floats2half2_rn(v.z, v.w);
}

// ---------------- fp16 GEMM: C = A[M,K] @ B[N,K]^T + bias ------------------
// CTA 128x128, BK=32, 3-stage cp.async, 4 warps (64x64 warp tile), ldmatrix.
#define ROWB   80                      /* bytes per smem row: 64 data + 16 pad */
#define ARRB   (128 * ROWB)            /* 10240 B per operand array            */
#define OFF_A  0
#define OFF_B  ARRB
#define STAGEB (2 * ARRB)              /* 20480 B per stage                    */
#define GEMM_SMEM (3 * STAGEB)         /* 61440 B                              */

__device__ __forceinline__ uint32_t smem_u32(const void* p) {
    uint32_t a;
    asm("{ .reg .u64 t; cvta.to.shared.u64 t, %1; cvt.u32.u64 %0, t; }" : "=r"(a) : "l"(p));
    return a;
}

__device__ __forceinline__ void cp16(uint32_t dst, const void* src, unsigned bytes) {
    asm volatile("cp.async.cg.shared.global [%0], [%1], 16, %2;"
                 :: "r"(dst), "l"(src), "r"(bytes) : "memory");
}

__device__ __forceinline__ void ldsm4(unsigned& r0, unsigned& r1, unsigned& r2, unsigned& r3,
                                      uint32_t addr) {
    asm volatile("ldmatrix.sync.aligned.m8n8.x4.shared.b16 {%0,%1,%2,%3}, [%4];"
                 : "=r"(r0), "=r"(r1), "=r"(r2), "=r"(r3) : "r"(addr));
}

__device__ __forceinline__ void mma_f16(float* c, const unsigned* a, unsigned b0, unsigned b1) {
    asm volatile(
        "mma.sync.aligned.m16n8k16.row.col.f32.f16.f16.f32 "
        "{%0,%1,%2,%3}, {%4,%5,%6,%7}, {%8,%9}, {%0,%1,%2,%3};\n"
        : "+f"(c[0]), "+f"(c[1]), "+f"(c[2]), "+f"(c[3])
        : "r"(a[0]), "r"(a[1]), "r"(a[2]), "r"(a[3]), "r"(b0), "r"(b1));
}

__global__ __launch_bounds__(128) void gemm_fp16(
    const __half* __restrict__ A, const __half* __restrict__ B,
    const float* __restrict__ bias, float* __restrict__ C,
    int M, int N, int K)
{
    extern __shared__ __align__(128) char smem[];
    uint32_t sb = smem_u32(smem);

    int tid  = threadIdx.x;
    int warp = tid >> 5, lane = tid & 31;
    int wm = warp >> 1, wn = warp & 1;           // 2x2 warps; warp tile 64x64
    int quad = lane >> 2, t4 = lane & 3;
    int m0 = blockIdx.y * 128, n0 = blockIdx.x * 128;
    int nk = K >> 5;

    // ldmatrix per-lane address components
    int rowoff_a = ((lane >> 3) & 1) * 8 + (lane & 7);   // g0/g2: rows 0-7, g1/g3: 8-15
    int koff_a   = (lane >> 4) * 16;                     // g2,g3: +16B (k 8-15)
    int rowoff_b = ((lane >> 4) & 1) * 8 + (lane & 7);   // g2,g3: second n8 block
    int koff_b   = ((lane >> 3) & 1) * 16;               // g1,g3: +16B (k 8-15)

    float acc[4][8][4];
    #pragma unroll
    for (int i = 0; i < 4; i++)
        #pragma unroll
        for (int j = 0; j < 8; j++)
            #pragma unroll
            for (int c = 0; c < 4; c++) acc[i][j][c] = 0.f;

    auto issue_stage = [&](int kc) {
        int slot = kc % 3;
        uint32_t stb = sb + slot * STAGEB;
        int kx = kc * 32;
        #pragma unroll
        for (int j = 0; j < 4; j++) {
            int chunk = j * 128 + tid;           // 0..511
            int row = chunk >> 2, kcx = chunk & 3;
            uint32_t doff = row * ROWB + kcx * 16;
            int gm = m0 + row;
            int gmc = gm < M ? gm : M - 1;
            cp16(stb + OFF_A + doff, A + (size_t)gmc * K + kx + kcx * 8,
                 gm < M ? 16u : 0u);
            cp16(stb + OFF_B + doff, B + (size_t)(n0 + row) * K + kx + kcx * 8, 16u);
        }
    };

    issue_stage(0);
    asm volatile("cp.async.commit_group;" ::: "memory");
    issue_stage(1);
    asm volatile("cp.async.commit_group;" ::: "memory");

    for (int kc = 0; kc < nk; kc++) {
        asm volatile("cp.async.wait_group 1;" ::: "memory");
        __syncthreads();
        if (kc + 2 < nk) issue_stage(kc + 2);
        asm volatile("cp.async.commit_group;" ::: "memory");

        int slot = kc % 3;
        uint32_t aBase = sb + slot * STAGEB + OFF_A + (wm * 64 + rowoff_a) * ROWB + koff_a;
        uint32_t bBase = sb + slot * STAGEB + OFF_B + (wn * 64 + rowoff_b) * ROWB + koff_b;

        #pragma unroll
        for (int ks = 0; ks < 2; ks++) {
            uint32_t ak = aBase + ks * 32;
            uint32_t bk = bBase + ks * 32;
            unsigned a[4][4], b[8][2];
            #pragma unroll
            for (int mi = 0; mi < 4; mi++)
                ldsm4(a[mi][0], a[mi][1], a[mi][2], a[mi][3], ak + mi * 16 * ROWB);
            #pragma unroll
            for (int nj = 0; nj < 4; nj++)
                ldsm4(b[nj * 2][0], b[nj * 2][1], b[nj * 2 + 1][0], b[nj * 2 + 1][1],
                      bk + nj * 16 * ROWB);
            #pragma unroll
            for (int mi = 0; mi < 4; mi++)
                #pragma unroll
                for (int ni = 0; ni < 8; ni++)
                    mma_f16(acc[mi][ni], a[mi], b[ni][0], b[ni][1]);
        }
    }

    #pragma unroll
    for (int mi = 0; mi < 4; mi++) {
        int gm = m0 + wm * 64 + mi * 16 + quad;
        #pragma unroll
        for (int ni = 0; ni < 8; ni++) {
            int gn = n0 + wn * 64 + ni * 8 + t4 * 2;
            float b0v = bias[gn], b1v = bias[gn + 1];
            if (gm < M)
                *(float2*)(C + (size_t)gm * N + gn) =
                    make_float2(acc[mi][ni][0] + b0v, acc[mi][ni][1] + b1v);
            if (gm + 8 < M)
                *(float2*)(C + (size_t)(gm + 8) * N + gn) =
                    make_float2(acc[mi][ni][2] + b0v, acc[mi][ni][3] + b1v);
        }
    }
}

// ---------------- min/max of the two x_ref_attn_map rows -------------------
__global__ void minmax_kernel(const float* __restrict__ xmap) {
    int row = blockIdx.x;
    const float* p = xmap + row * NTOK;
    float mn = 3.4e38f, mx = -3.4e38f;
    for (int i = threadIdx.x; i < NTOK; i += blockDim.x) {
        float v = p[i];
        mn = fminf(mn, v); mx = fmaxf(mx, v);
    }
    __shared__ float smn[32], smx[32];
    int lane = threadIdx.x & 31, w = threadIdx.x >> 5;
    #pragma unroll
    for (int o = 16; o; o >>= 1) {
        mn = fminf(mn, __shfl_xor_sync(0xffffffffu, mn, o));
        mx = fmaxf(mx, __shfl_xor_sync(0xffffffffu, mx, o));
    }
    if (lane == 0) { smn[w] = mn; smx[w] = mx; }
    __syncthreads();
    if (w == 0) {
        int nw = blockDim.x >> 5;
        mn = (lane < nw) ? smn[lane] :  3.4e38f;
        mx = (lane < nw) ? smx[lane] : -3.4e38f;
        #pragma unroll
        for (int o = 16; o; o >>= 1) {
            mn = fminf(mn, __shfl_xor_sync(0xffffffffu, mn, o));
            mx = fmaxf(mx, __shfl_xor_sync(0xffffffffu, mx, o));
        }
        if (lane == 0) { g_minmax[row * 2] = mn; g_minmax[row * 2 + 1] = mx; }
    }
}

// ------------- q: LayerNorm(eps 1e-6) + RoPE (remapped per-token pos) ------
__global__ __launch_bounds__(256) void ln_rope_q(const float* __restrict__ xmap,
                                                 const float* __restrict__ gamma,
                                                 const float* __restrict__ beta) {
    int gw   = blockIdx.x * 8 + (threadIdx.x >> 5);
    int lane = threadIdx.x & 31;
    int r = gw / NH;
    int h = gw - r * NH;
    float* row = g_Q + (size_t)r * DIMC + h * HDIM;
    float4 v = *(float4*)(row + lane * 4);

    float s  = v.x + v.y + v.z + v.w;
    float sq = v.x * v.x + v.y * v.y + v.z * v.z + v.w * v.w;
    #pragma unroll
    for (int o = 16; o; o >>= 1) {
        s  += __shfl_xor_sync(0xffffffffu, s,  o);
        sq += __shfl_xor_sync(0xffffffffu, sq, o);
    }
    float mean = s * (1.f / HDIM);
    float var  = sq * (1.f / HDIM) - mean * mean;
    float rs   = rsqrtf(var + 1e-6f);

    float4 gg = *(const float4*)(gamma + lane * 4);
    float4 bb = *(const float4*)(beta  + lane * 4);
    v.x = (v.x - mean) * rs * gg.x + bb.x;
    v.y = (v.y - mean) * rs * gg.y + bb.y;
    v.z = (v.z - mean) * rs * gg.z + bb.z;
    v.w = (v.w - mean) * rs * gg.w + bb.w;

    int b = r >> 10, sidx = r & 1023;
    int l = (b * (NH * SEQ) + h * SEQ + sidx) % NTOK;
    float m0 = xmap[l], m1 = xmap[NTOK + l];
    float mn0 = g_minmax[0], mx0 = g_minmax[1], mn1 = g_minmax[2], mx1 = g_minmax[3];
    float pos = (m0 >= m1) ? (m0 - mn0) / (mx0 - mn0) * 4.0f
                           : (m1 - mn1) / (mx1 - mn1) * 4.0f + 20.0f;

    const float CF = -0.20762050593046868f;   // -2*log2(10000)/128
    int i0 = lane * 2;
    float f0 = exp2f((float)i0 * CF);
    float f1 = exp2f((float)(i0 + 1) * CF);
    float s0, c0, s1, c1;
    sincosf(pos * f0, &s0, &c0);
    sincosf(pos * f1, &s1, &c1);
    float4 o;
    o.x = v.x * c0 - v.y * s0;
    o.y = v.y * c0 + v.x * s0;
    o.z = v.z * c1 - v.w * s1;
    o.w = v.w * c1 + v.z * s1;
    *(float4*)(row + lane * 4) = o;
}

// ------------- k: LayerNorm(eps 1e-5) + RoPE (pos = 2 or 22) ---------------
__global__ __launch_bounds__(256) void k_ln_rope(const float* __restrict__ gamma,
                                                 const float* __restrict__ beta) {
    int gw   = blockIdx.x * 8 + (threadIdx.x >> 5);
    int lane = threadIdx.x & 31;
    int r = gw / NH;
    int h = gw - r * NH;
    float* row = g_KV + (size_t)r * (2 * DIMC) + h * HDIM;
    float4 v = *(float4*)(row + lane * 4);

    float s  = v.x + v.y + v.z + v.w;
    float sq = v.x * v.x + v.y * v.y + v.z * v.z + v.w * v.w;
    #pragma unroll
    for (int o = 16; o; o >>= 1) {
        s  += __shfl_xor_sync(0xffffffffu, s,  o);
        sq += __shfl_xor_sync(0xffffffffu, sq, o);
    }
    float mean = s * (1.f / HDIM);
    float var  = sq * (1.f / HDIM) - mean * mean;
    float rs   = rsqrtf(var + 1e-5f);

    float4 gg = *(const float4*)(gamma + lane * 4);
    float4 bb = *(const float4*)(beta  + lane * 4);
    v.x = (v.x - mean) * rs * gg.x + bb.x;
    v.y = (v.y - mean) * rs * gg.y + bb.y;
    v.z = (v.z - mean) * rs * gg.z + bb.z;
    v.w = (v.w - mean) * rs * gg.w + bb.w;

    int na = r & (NAK - 1);
    float pos = (na < NAK / 2) ? 2.0f : 22.0f;

    const float CF = -0.20762050593046868f;
    int i0 = lane * 2;
    float f0 = exp2f((float)i0 * CF);
    float f1 = exp2f((float)(i0 + 1) * CF);
    float s0, c0, s1, c1;
    sincosf(pos * f0, &s0, &c0);
    sincosf(pos * f1, &s1, &c1);
    float4 o;
    o.x = v.x * c0 - v.y * s0;
    o.y = v.y * c0 + v.x * s0;
    o.z = v.z * c1 - v.w * s1;
    o.w = v.w * c1 + v.z * s1;
    *(float4*)(row + lane * 4) = o;
}

// ------------- attention: per (b,h), NA=32 keys; fp16 output ---------------
#define VPAD 132
__global__ __launch_bounds__(256) void attn_kernel() {
    int bh = blockIdx.x;
    int b = bh / NH, h = bh - b * NH;
    __shared__ float ks[NAK][VPAD], vs[NAK][VPAD];
    int tid = threadIdx.x;
    for (int idx = tid; idx < NAK * HDIM; idx += 256) {
        int n = idx >> 7, d = idx & 127;
        size_t base = (size_t)(b * NAK + n) * (2 * DIMC) + h * HDIM + d;
        ks[n][d] = g_KV[base];
        vs[n][d] = g_KV[base + DIMC];
    }
    __syncthreads();

    int warp = tid >> 5, lane = tid & 31;
    const float SC = 0.08838834764831845f;
    for (int s = warp; s < SEQ; s += 8) {
        const float* q = g_Q + (size_t)(b * SEQ + s) * DIMC + h * HDIM;
        float sc = 0.f;
        #pragma unroll
        for (int d = 0; d < HDIM; d += 4) {
            float4 qv = *(const float4*)(q + d);
            float4 kv = *(const float4*)(&ks[lane][d]);
            sc += qv.x * kv.x + qv.y * kv.y + qv.z * kv.z + qv.w * kv.w;
        }
        sc *= SC;
        float mx = sc;
        #pragma unroll
        for (int o = 16; o; o >>= 1) mx = fmaxf(mx, __shfl_xor_sync(0xffffffffu, mx, o));
        float e = __expf(sc - mx);
        float sum = e;
        #pragma unroll
        for (int o = 16; o; o >>= 1) sum += __shfl_xor_sync(0xffffffffu, sum, o);
        float p = e / sum;

        float4 acc = make_float4(0.f, 0.f, 0.f, 0.f);
        #pragma unroll
        for (int n = 0; n < NAK; n++) {
            float pn = __shfl_sync(0xffffffffu, p, n);
            float4 vv = *(const float4*)(&vs[n][lane * 4]);
            acc.x += pn * vv.x; acc.y += pn * vv.y;
            acc.z += pn * vv.z; acc.w += pn * vv.w;
        }
        __half2* op = (__half2*)(g_oh + (size_t)(b * SEQ + s) * DIMC + h * HDIM + lane * 4);
        op[0] = __floats2half2_rn(acc.x, acc.y);
        op[1] = __floats2half2_rn(acc.z, acc.w);
    }
}

// ======================= host side =======================
static void conv1(const float* in, __half* out, size_t n) {
    int n4 = (int)(n / 4);
    convert_single_h<<<(n4 + 255) / 256, 256>>>((const float4*)in, (__half2*)out, n4);
}

extern "C" void kernel_launch(void* const* d_in, const int* in_sizes, int n_in,
                              void* d_out, int out_size) {
    const float* x     = (const float*)d_in[0];
    const float* enc_i = (const float*)d_in[1];
    const float* xmap  = (const float*)d_in[2];
    const float* q_w   = (const float*)d_in[3];
    const float* q_b   = (const float*)d_in[4];
    const float* kv_w  = (const float*)d_in[5];
    const float* kv_b  = (const float*)d_in[6];
    const float* prj_w = (const float*)d_in[7];
    const float* prj_b = (const float*)d_in[8];
    const float* qn_g  = (const float*)d_in[9];
    const float* qn_b  = (const float*)d_in[10];
    const float* kn_g  = (const float*)d_in[11];
    const float* kn_b  = (const float*)d_in[12];
    float* out = (float*)d_out;

    float *Q, *KV;
    __half *xh, *oh, *eh, *wqh, *wph, *wkh;
    cudaGetSymbolAddress((void**)&Q,   g_Q);
    cudaGetSymbolAddress((void**)&KV,  g_KV);
    cudaGetSymbolAddress((void**)&xh,  g_xh);
    cudaGetSymbolAddress((void**)&oh,  g_oh);
    cudaGetSymbolAddress((void**)&eh,  g_eh);
    cudaGetSymbolAddress((void**)&wqh, g_wqh);
    cudaGetSymbolAddress((void**)&wph, g_wph);
    cudaGetSymbolAddress((void**)&wkh, g_wkh);

    cudaFuncSetAttribute(gemm_fp16, cudaFuncAttributeMaxDynamicSharedMemorySize, GEMM_SMEM);

    minmax_kernel<<<2, 256>>>(xmap);

    conv1(x,     xh,  (size_t)NTOK * DIMC);
    conv1(enc_i, eh,  (size_t)ENCR * ENCC);
    conv1(q_w,   wqh, (size_t)DIMC * DIMC);
    conv1(kv_w,  wkh, (size_t)2 * DIMC * ENCC);
    conv1(prj_w, wph, (size_t)DIMC * DIMC);

    // GEMM 1: Q = x @ q_w^T   [21504 x 3072] x [3072 x 3072]
    gemm_fp16<<<dim3(DIMC / 128, NTOK / 128), 128, GEMM_SMEM>>>(
        xh, wqh, q_b, Q, NTOK, DIMC, DIMC);

    // GEMM 2: KV = enc @ kv_w^T   [672 x 768] x [6144 x 768]
    gemm_fp16<<<dim3((2 * DIMC) / 128, (ENCR + 127) / 128), 128, GEMM_SMEM>>>(
        eh, wkh, kv_b, KV, ENCR, 2 * DIMC, ENCC);

    ln_rope_q<<<(NTOK * NH) / 8, 256>>>(xmap, qn_g, qn_b);
    k_ln_rope<<<(ENCR * NH) / 8, 256>>>(kn_g, kn_b);

    attn_kernel<<<N_T * NH, 256>>>();

    // GEMM 3: out = attn_out @ prj_w^T
    gemm_fp16<<<dim3(DIMC / 128, NTOK / 128), 128, GEMM_SMEM>>>(
        oh, wph, prj_b, out, NTOK, DIMC, DIMC);
}

// round 11
// speedup vs baseline: 3.0546x; 1.3536x over previous
#include <cuda_runtime.h>
#include <cuda_fp16.h>
#include <cstdint>

#define N_T   21
#define SEQ   1024
#define DIMC  3072
#define NH    24
#define HDIM  128
#define ENCC  768
#define NAK   32
#define NTOK  (N_T * SEQ)          /* 21504 */
#define ENCR  (N_T * NAK)          /* 672 */

// ---------------- scratch (device globals: allocation-free) ----------------
__device__ float g_KV[(size_t)ENCR * 2 * DIMC];
__device__ float g_minmax[4];

__device__ __half g_qh [(size_t)NTOK * DIMC];      // Q fp16 (GEMM1 out, LN/RoPE in-place)
__device__ __half g_xh [(size_t)NTOK * DIMC];      // activations fp16
__device__ __half g_oh [(size_t)NTOK * DIMC];      // attn output fp16
__device__ __half g_eh [(size_t)ENCR * ENCC];
__device__ __half g_wqh[(size_t)DIMC * DIMC];      // weights fp16
__device__ __half g_wph[(size_t)DIMC * DIMC];
__device__ __half g_wkh[(size_t)2 * DIMC * ENCC];

// ---------------- conversions ----------------------------------------------
__global__ __launch_bounds__(256) void convert_single_h(
    const float4* __restrict__ in, __half2* __restrict__ out, int n4)
{
    int i = blockIdx.x * 256 + threadIdx.x;
    if (i >= n4) return;
    float4 v = in[i];
    out[2 * i]     = __floats2half2_rn(v.x, v.y);
    out[2 * i + 1] = __floats2half2_rn(v.z, v.w);
}

// ---------------- fp16 GEMM: C = A[M,K] @ B[N,K]^T + bias ------------------
// CTA 128x128, BK=64, 3-stage cp.async, 4 warps (64x64 warp tile), ldmatrix.
#define ROWB   144                     /* bytes per smem row: 128 data + 16 pad */
#define ARRB   (128 * ROWB)            /* 18432 B per operand array             */
#define OFF_A  0
#define OFF_B  ARRB
#define STAGEB (2 * ARRB)              /* 36864 B per stage                     */
#define GEMM_SMEM (3 * STAGEB)         /* 110592 B                              */

__device__ __forceinline__ uint32_t smem_u32(const void* p) {
    uint32_t a;
    asm("{ .reg .u64 t; cvta.to.shared.u64 t, %1; cvt.u32.u64 %0, t; }" : "=r"(a) : "l"(p));
    return a;
}

__device__ __forceinline__ void cp16(uint32_t dst, const void* src, unsigned bytes) {
    asm volatile("cp.async.cg.shared.global [%0], [%1], 16, %2;"
                 :: "r"(dst), "l"(src), "r"(bytes) : "memory");
}

__device__ __forceinline__ void ldsm4(unsigned& r0, unsigned& r1, unsigned& r2, unsigned& r3,
                                      uint32_t addr) {
    asm volatile("ldmatrix.sync.aligned.m8n8.x4.shared.b16 {%0,%1,%2,%3}, [%4];"
                 : "=r"(r0), "=r"(r1), "=r"(r2), "=r"(r3) : "r"(addr));
}

__device__ __forceinline__ void mma_f16(float* c, const unsigned* a, unsigned b0, unsigned b1) {
    asm volatile(
        "mma.sync.aligned.m16n8k16.row.col.f32.f16.f16.f32 "
        "{%0,%1,%2,%3}, {%4,%5,%6,%7}, {%8,%9}, {%0,%1,%2,%3};\n"
        : "+f"(c[0]), "+f"(c[1]), "+f"(c[2]), "+f"(c[3])
        : "r"(a[0]), "r"(a[1]), "r"(a[2]), "r"(a[3]), "r"(b0), "r"(b1));
}

__device__ __forceinline__ void store_pair(float* p, float a, float b) {
    *(float2*)p = make_float2(a, b);
}
__device__ __forceinline__ void store_pair(__half* p, float a, float b) {
    *(__half2*)p = __floats2half2_rn(a, b);
}

template <typename TO>
__global__ __launch_bounds__(128) void gemm_fp16(
    const __half* __restrict__ A, const __half* __restrict__ B,
    const float* __restrict__ bias, TO* __restrict__ C,
    int M, int N, int K)
{
    extern __shared__ __align__(128) char smem[];
    uint32_t sb = smem_u32(smem);

    int tid  = threadIdx.x;
    int warp = tid >> 5, lane = tid & 31;
    int wm = warp >> 1, wn = warp & 1;           // 2x2 warps; warp tile 64x64
    int quad = lane >> 2, t4 = lane & 3;
    int m0 = blockIdx.y * 128, n0 = blockIdx.x * 128;
    int nk = K >> 6;

    // ldmatrix per-lane address components
    int rowoff_a = ((lane >> 3) & 1) * 8 + (lane & 7);
    int koff_a   = (lane >> 4) * 16;
    int rowoff_b = ((lane >> 4) & 1) * 8 + (lane & 7);
    int koff_b   = ((lane >> 3) & 1) * 16;

    float acc[4][8][4];
    #pragma unroll
    for (int i = 0; i < 4; i++)
        #pragma unroll
        for (int j = 0; j < 8; j++)
            #pragma unroll
            for (int c = 0; c < 4; c++) acc[i][j][c] = 0.f;

    auto issue_stage = [&](int kc) {
        int slot = kc % 3;
        uint32_t stb = sb + slot * STAGEB;
        int kx = kc * 64;
        #pragma unroll
        for (int j = 0; j < 8; j++) {
            int chunk = j * 128 + tid;           // 0..1023
            int row = chunk >> 3, kcx = chunk & 7;
            uint32_t doff = row * ROWB + kcx * 16;
            int gm = m0 + row;
            int gmc = gm < M ? gm : M - 1;
            cp16(stb + OFF_A + doff, A + (size_t)gmc * K + kx + kcx * 8,
                 gm < M ? 16u : 0u);
            cp16(stb + OFF_B + doff, B + (size_t)(n0 + row) * K + kx + kcx * 8, 16u);
        }
    };

    issue_stage(0);
    asm volatile("cp.async.commit_group;" ::: "memory");
    issue_stage(1);
    asm volatile("cp.async.commit_group;" ::: "memory");

    for (int kc = 0; kc < nk; kc++) {
        asm volatile("cp.async.wait_group 1;" ::: "memory");
        __syncthreads();
        if (kc + 2 < nk) issue_stage(kc + 2);
        asm volatile("cp.async.commit_group;" ::: "memory");

        int slot = kc % 3;
        uint32_t aBase = sb + slot * STAGEB + OFF_A + (wm * 64 + rowoff_a) * ROWB + koff_a;
        uint32_t bBase = sb + slot * STAGEB + OFF_B + (wn * 64 + rowoff_b) * ROWB + koff_b;

        #pragma unroll
        for (int ks = 0; ks < 4; ks++) {
            uint32_t ak = aBase + ks * 32;
            uint32_t bk = bBase + ks * 32;
            unsigned a[4][4], b[8][2];
            #pragma unroll
            for (int mi = 0; mi < 4; mi++)
                ldsm4(a[mi][0], a[mi][1], a[mi][2], a[mi][3], ak + mi * 16 * ROWB);
            #pragma unroll
            for (int nj = 0; nj < 4; nj++)
                ldsm4(b[nj * 2][0], b[nj * 2][1], b[nj * 2 + 1][0], b[nj * 2 + 1][1],
                      bk + nj * 16 * ROWB);
            #pragma unroll
            for (int mi = 0; mi < 4; mi++)
                #pragma unroll
                for (int ni = 0; ni < 8; ni++)
                    mma_f16(acc[mi][ni], a[mi], b[ni][0], b[ni][1]);
        }
    }

    #pragma unroll
    for (int mi = 0; mi < 4; mi++) {
        int gm = m0 + wm * 64 + mi * 16 + quad;
        #pragma unroll
        for (int ni = 0; ni < 8; ni++) {
            int gn = n0 + wn * 64 + ni * 8 + t4 * 2;
            float b0v = bias[gn], b1v = bias[gn + 1];
            if (gm < M)
                store_pair(C + (size_t)gm * N + gn,
                           acc[mi][ni][0] + b0v, acc[mi][ni][1] + b1v);
            if (gm + 8 < M)
                store_pair(C + (size_t)(gm + 8) * N + gn,
                           acc[mi][ni][2] + b0v, acc[mi][ni][3] + b1v);
        }
    }
}

// ---------------- min/max of the two x_ref_attn_map rows -------------------
__global__ void minmax_kernel(const float* __restrict__ xmap) {
    int row = blockIdx.x;
    const float* p = xmap + row * NTOK;
    float mn = 3.4e38f, mx = -3.4e38f;
    for (int i = threadIdx.x; i < NTOK; i += blockDim.x) {
        float v = p[i];
        mn = fminf(mn, v); mx = fmaxf(mx, v);
    }
    __shared__ float smn[32], smx[32];
    int lane = threadIdx.x & 31, w = threadIdx.x >> 5;
    #pragma unroll
    for (int o = 16; o; o >>= 1) {
        mn = fminf(mn, __shfl_xor_sync(0xffffffffu, mn, o));
        mx = fmaxf(mx, __shfl_xor_sync(0xffffffffu, mx, o));
    }
    if (lane == 0) { smn[w] = mn; smx[w] = mx; }
    __syncthreads();
    if (w == 0) {
        int nw = blockDim.x >> 5;
        mn = (lane < nw) ? smn[lane] :  3.4e38f;
        mx = (lane < nw) ? smx[lane] : -3.4e38f;
        #pragma unroll
        for (int o = 16; o; o >>= 1) {
            mn = fminf(mn, __shfl_xor_sync(0xffffffffu, mn, o));
            mx = fmaxf(mx, __shfl_xor_sync(0xffffffffu, mx, o));
        }
        if (lane == 0) { g_minmax[row * 2] = mn; g_minmax[row * 2 + 1] = mx; }
    }
}

// ------------- q: LayerNorm(eps 1e-6) + RoPE, fp16 in/out ------------------
__global__ __launch_bounds__(256) void ln_rope_q(const float* __restrict__ xmap,
                                                 const float* __restrict__ gamma,
                                                 const float* __restrict__ beta) {
    int gw   = blockIdx.x * 8 + (threadIdx.x >> 5);
    int lane = threadIdx.x & 31;
    int r = gw / NH;
    int h = gw - r * NH;
    __half2* row = (__half2*)(g_qh + (size_t)r * DIMC + h * HDIM);
    __half2 p0 = row[lane * 2], p1 = row[lane * 2 + 1];
    float4 v;
    { float2 f0 = __half22float2(p0), f1 = __half22float2(p1);
      v.x = f0.x; v.y = f0.y; v.z = f1.x; v.w = f1.y; }

    float s  = v.x + v.y + v.z + v.w;
    float sq = v.x * v.x + v.y * v.y + v.z * v.z + v.w * v.w;
    #pragma unroll
    for (int o = 16; o; o >>= 1) {
        s  += __shfl_xor_sync(0xffffffffu, s,  o);
        sq += __shfl_xor_sync(0xffffffffu, sq, o);
    }
    float mean = s * (1.f / HDIM);
    float var  = sq * (1.f / HDIM) - mean * mean;
    float rs   = rsqrtf(var + 1e-6f);

    float4 gg = *(const float4*)(gamma + lane * 4);
    float4 bb = *(const float4*)(beta  + lane * 4);
    v.x = (v.x - mean) * rs * gg.x + bb.x;
    v.y = (v.y - mean) * rs * gg.y + bb.y;
    v.z = (v.z - mean) * rs * gg.z + bb.z;
    v.w = (v.w - mean) * rs * gg.w + bb.w;

    int b = r >> 10, sidx = r & 1023;
    int l = (b * (NH * SEQ) + h * SEQ + sidx) % NTOK;
    float m0 = xmap[l], m1 = xmap[NTOK + l];
    float mn0 = g_minmax[0], mx0 = g_minmax[1], mn1 = g_minmax[2], mx1 = g_minmax[3];
    float pos = (m0 >= m1) ? (m0 - mn0) / (mx0 - mn0) * 4.0f
                           : (m1 - mn1) / (mx1 - mn1) * 4.0f + 20.0f;

    const float CF = -0.20762050593046868f;   // -2*log2(10000)/128
    int i0 = lane * 2;
    float f0 = exp2f((float)i0 * CF);
    float f1 = exp2f((float)(i0 + 1) * CF);
    float s0, c0, s1, c1;
    sincosf(pos * f0, &s0, &c0);
    sincosf(pos * f1, &s1, &c1);
    row[lane * 2]     = __floats2half2_rn(v.x * c0 - v.y * s0, v.y * c0 + v.x * s0);
    row[lane * 2 + 1] = __floats2half2_rn(v.z * c1 - v.w * s1, v.w * c1 + v.z * s1);
}

// ------------- k: LayerNorm(eps 1e-5) + RoPE (pos = 2 or 22) ---------------
__global__ __launch_bounds__(256) void k_ln_rope(const float* __restrict__ gamma,
                                                 const float* __restrict__ beta) {
    int gw   = blockIdx.x * 8 + (threadIdx.x >> 5);
    int lane = threadIdx.x & 31;
    int r = gw / NH;
    int h = gw - r * NH;
    float* row = g_KV + (size_t)r * (2 * DIMC) + h * HDIM;
    float4 v = *(float4*)(row + lane * 4);

    float s  = v.x + v.y + v.z + v.w;
    float sq = v.x * v.x + v.y * v.y + v.z * v.z + v.w * v.w;
    #pragma unroll
    for (int o = 16; o; o >>= 1) {
        s  += __shfl_xor_sync(0xffffffffu, s,  o);
        sq += __shfl_xor_sync(0xffffffffu, sq, o);
    }
    float mean = s * (1.f / HDIM);
    float var  = sq * (1.f / HDIM) - mean * mean;
    float rs   = rsqrtf(var + 1e-5f);

    float4 gg = *(const float4*)(gamma + lane * 4);
    float4 bb = *(const float4*)(beta  + lane * 4);
    v.x = (v.x - mean) * rs * gg.x + bb.x;
    v.y = (v.y - mean) * rs * gg.y + bb.y;
    v.z = (v.z - mean) * rs * gg.z + bb.z;
    v.w = (v.w - mean) * rs * gg.w + bb.w;

    int na = r & (NAK - 1);
    float pos = (na < NAK / 2) ? 2.0f : 22.0f;

    const float CF = -0.20762050593046868f;
    int i0 = lane * 2;
    float f0 = exp2f((float)i0 * CF);
    float f1 = exp2f((float)(i0 + 1) * CF);
    float s0, c0, s1, c1;
    sincosf(pos * f0, &s0, &c0);
    sincosf(pos * f1, &s1, &c1);
    float4 o;
    o.x = v.x * c0 - v.y * s0;
    o.y = v.y * c0 + v.x * s0;
    o.z = v.z * c1 - v.w * s1;
    o.w = v.w * c1 + v.z * s1;
    *(float4*)(row + lane * 4) = o;
}

// ------------- attention: per (b,h), NA=32 keys; fp16 q in, fp16 out -------
#define VPAD 132
__global__ __launch_bounds__(256) void attn_kernel() {
    int bh = blockIdx.x;
    int b = bh / NH, h = bh - b * NH;
    __shared__ float ks[NAK][VPAD], vs[NAK][VPAD];
    int tid = threadIdx.x;
    for (int idx = tid; idx < NAK * HDIM; idx += 256) {
        int n = idx >> 7, d = idx & 127;
        size_t base = (size_t)(b * NAK + n) * (2 * DIMC) + h * HDIM + d;
        ks[n][d] = g_KV[base];
        vs[n][d] = g_KV[base + DIMC];
    }
    __syncthreads();

    int warp = tid >> 5, lane = tid & 31;
    const float SC = 0.08838834764831845f;
    for (int s = warp; s < SEQ; s += 8) {
        const __half2* q = (const __half2*)(g_qh + (size_t)(b * SEQ + s) * DIMC + h * HDIM);
        float sc = 0.f;
        #pragma unroll
        for (int d = 0; d < HDIM; d += 4) {
            float2 q0 = __half22float2(q[d / 2]);
            float2 q1 = __half22float2(q[d / 2 + 1]);
            float4 kv = *(const float4*)(&ks[lane][d]);
            sc += q0.x * kv.x + q0.y * kv.y + q1.x * kv.z + q1.y * kv.w;
        }
        sc *= SC;
        float mx = sc;
        #pragma unroll
        for (int o = 16; o; o >>= 1) mx = fmaxf(mx, __shfl_xor_sync(0xffffffffu, mx, o));
        float e = __expf(sc - mx);
        float sum = e;
        #pragma unroll
        for (int o = 16; o; o >>= 1) sum += __shfl_xor_sync(0xffffffffu, sum, o);
        float p = e / sum;

        float4 acc = make_float4(0.f, 0.f, 0.f, 0.f);
        #pragma unroll
        for (int n = 0; n < NAK; n++) {
            float pn = __shfl_sync(0xffffffffu, p, n);
            float4 vv = *(const float4*)(&vs[n][lane * 4]);
            acc.x += pn * vv.x; acc.y += pn * vv.y;
            acc.z += pn * vv.z; acc.w += pn * vv.w;
        }
        __half2* op = (__half2*)(g_oh + (size_t)(b * SEQ + s) * DIMC + h * HDIM + lane * 4);
        op[0] = __floats2half2_rn(acc.x, acc.y);
        op[1] = __floats2half2_rn(acc.z, acc.w);
    }
}

// ======================= host side =======================
static void conv1(const float* in, __half* out, size_t n) {
    int n4 = (int)(n / 4);
    convert_single_h<<<(n4 + 255) / 256, 256>>>((const float4*)in, (__half2*)out, n4);
}

extern "C" void kernel_launch(void* const* d_in, const int* in_sizes, int n_in,
                              void* d_out, int out_size) {
    const float* x     = (const float*)d_in[0];
    const float* enc_i = (const float*)d_in[1];
    const float* xmap  = (const float*)d_in[2];
    const float* q_w   = (const float*)d_in[3];
    const float* q_b   = (const float*)d_in[4];
    const float* kv_w  = (const float*)d_in[5];
    const float* kv_b  = (const float*)d_in[6];
    const float* prj_w = (const float*)d_in[7];
    const float* prj_b = (const float*)d_in[8];
    const float* qn_g  = (const float*)d_in[9];
    const float* qn_b  = (const float*)d_in[10];
    const float* kn_g  = (const float*)d_in[11];
    const float* kn_b  = (const float*)d_in[12];
    float* out = (float*)d_out;

    float *KV;
    __half *qh, *xh, *oh, *eh, *wqh, *wph, *wkh;
    cudaGetSymbolAddress((void**)&KV,  g_KV);
    cudaGetSymbolAddress((void**)&qh,  g_qh);
    cudaGetSymbolAddress((void**)&xh,  g_xh);
    cudaGetSymbolAddress((void**)&oh,  g_oh);
    cudaGetSymbolAddress((void**)&eh,  g_eh);
    cudaGetSymbolAddress((void**)&wqh, g_wqh);
    cudaGetSymbolAddress((void**)&wph, g_wph);
    cudaGetSymbolAddress((void**)&wkh, g_wkh);

    cudaFuncSetAttribute(gemm_fp16<float>,  cudaFuncAttributeMaxDynamicSharedMemorySize, GEMM_SMEM);
    cudaFuncSetAttribute(gemm_fp16<__half>, cudaFuncAttributeMaxDynamicSharedMemorySize, GEMM_SMEM);

    // launches 1-5: conversions  (6th launch = GEMM1 -> ncu -s 5 captures it)
    conv1(x,     xh,  (size_t)NTOK * DIMC);
    conv1(enc_i, eh,  (size_t)ENCR * ENCC);
    conv1(q_w,   wqh, (size_t)DIMC * DIMC);
    conv1(kv_w,  wkh, (size_t)2 * DIMC * ENCC);
    conv1(prj_w, wph, (size_t)DIMC * DIMC);

    // GEMM 1: Q(fp16) = x @ q_w^T   [21504 x 3072] x [3072 x 3072]
    gemm_fp16<__half><<<dim3(DIMC / 128, NTOK / 128), 128, GEMM_SMEM>>>(
        xh, wqh, q_b, qh, NTOK, DIMC, DIMC);

    // GEMM 2: KV = enc @ kv_w^T   [672 x 768] x [6144 x 768]
    gemm_fp16<float><<<dim3((2 * DIMC) / 128, (ENCR + 127) / 128), 128, GEMM_SMEM>>>(
        eh, wkh, kv_b, KV, ENCR, 2 * DIMC, ENCC);

    minmax_kernel<<<2, 256>>>(xmap);

    ln_rope_q<<<(NTOK * NH) / 8, 256>>>(xmap, qn_g, qn_b);
    k_ln_rope<<<(ENCR * NH) / 8, 256>>>(kn_g, kn_b);

    attn_kernel<<<N_T * NH, 256>>>();

    // GEMM 3: out = attn_out @ prj_w^T
    gemm_fp16<float><<<dim3(DIMC / 128, NTOK / 128), 128, GEMM_SMEM>>>(
        oh, wph, prj_b, out, NTOK, DIMC, DIMC);
}